// round 1
// baseline (speedup 1.0000x reference)
#include <cuda_runtime.h>
#include <cuda_bf16.h>
#include <math.h>

#define D_IN   768
#define D_OUT  256
#define NEXP   8
#define NT_MAX 32768

// Scratch (device globals — no allocation allowed)
__device__ int   g_cnt[NEXP];
__device__ int   g_tok[NEXP * NT_MAX];
__device__ float g_wt [NEXP * NT_MAX];

__global__ void zero_cnt_kernel() {
    if (threadIdx.x < NEXP) g_cnt[threadIdx.x] = 0;
}

// One warp per token: gate logits -> softmax -> top2 -> append to expert lists.
__global__ void gate_kernel(const float* __restrict__ x,
                            const float* __restrict__ gW,
                            const float* __restrict__ gb,
                            int NT) {
    __shared__ float sW[D_IN * NEXP];  // 24 KB
    for (int i = threadIdx.x; i < D_IN * NEXP; i += blockDim.x) sW[i] = gW[i];
    __syncthreads();

    int warp = threadIdx.x >> 5;
    int lane = threadIdx.x & 31;
    int token = blockIdx.x * (blockDim.x >> 5) + warp;
    if (token >= NT) return;

    const float* xr = x + (size_t)token * D_IN;
    float acc[NEXP];
#pragma unroll
    for (int e = 0; e < NEXP; e++) acc[e] = 0.f;

#pragma unroll
    for (int j = 0; j < D_IN / 32; j++) {
        int k = lane + j * 32;
        float xv = xr[k];
        const float* w = &sW[k * NEXP];
#pragma unroll
        for (int e = 0; e < NEXP; e++) acc[e] = fmaf(xv, w[e], acc[e]);
    }
#pragma unroll
    for (int off = 16; off > 0; off >>= 1) {
#pragma unroll
        for (int e = 0; e < NEXP; e++)
            acc[e] += __shfl_xor_sync(0xffffffffu, acc[e], off);
    }

    if (lane == 0) {
        float l[NEXP];
#pragma unroll
        for (int e = 0; e < NEXP; e++) l[e] = acc[e] + gb[e];
        float m = l[0];
#pragma unroll
        for (int e = 1; e < NEXP; e++) m = fmaxf(m, l[e]);
        float s = 0.f, w[NEXP];
#pragma unroll
        for (int e = 0; e < NEXP; e++) { w[e] = __expf(l[e] - m); s += w[e]; }
        float inv = 1.f / s;

        // top-2 on logits (softmax monotonic); strict > keeps lowest index on ties
        int i0 = 0;
#pragma unroll
        for (int e = 1; e < NEXP; e++) if (l[e] > l[i0]) i0 = e;
        int i1 = (i0 == 0) ? 1 : 0;
#pragma unroll
        for (int e = 0; e < NEXP; e++)
            if (e != i0 && l[e] > l[i1]) i1 = e;

        float w0 = w[i0] * inv, w1 = w[i1] * inv;
        int p0 = atomicAdd(&g_cnt[i0], 1);
        g_tok[i0 * NT_MAX + p0] = token;
        g_wt [i0 * NT_MAX + p0] = w0;
        int p1 = atomicAdd(&g_cnt[i1], 1);
        g_tok[i1 * NT_MAX + p1] = token;
        g_wt [i1 * NT_MAX + p1] = w1;
    }
}

// Per-expert gathered SGEMM: BM=128, BN=64, BK=16, 256 thr, 8x4 micro-tile.
// grid = (D_OUT/64, maxMTiles, NEXP). Epilogue: atomicAdd(out, w*(acc+b)).
#define BM 128
#define BN 64
#define BK 16
#define TM 8
#define TN 4

__global__ __launch_bounds__(256, 4)
void moe_gemm_kernel(const float* __restrict__ x,
                     const float* __restrict__ eW,
                     const float* __restrict__ eb,
                     float* __restrict__ out,
                     int NT) {
    const int e = blockIdx.z;
    const int cnt = g_cnt[e];
    const int mbase = blockIdx.y * BM;
    if (mbase >= cnt) return;
    const int nbase = blockIdx.x * BN;

    __shared__ float As[BK][BM + 1];   // +1 pad: conflict-free transposed store
    __shared__ float Bs[BK][BN];

    const int tid = threadIdx.x;
    const int ty = tid >> 4;           // 0..15 -> rows
    const int tx = tid & 15;           // 0..15 -> cols

    const int* toks = g_tok + e * NT_MAX + mbase;
    const float* wE = eW + (size_t)e * D_IN * D_OUT;

    // Row pointers for the two A-load slots this thread owns
    int   rowA[2];
    const float* rowPtr[2];
#pragma unroll
    for (int i = 0; i < 2; i++) {
        int slot = tid + i * 256;      // 512 slots = 128 rows x 4 float4 chunks
        int r = slot >> 2;
        rowA[i] = r;
        rowPtr[i] = (mbase + r < cnt) ? x + (size_t)toks[r] * D_IN : nullptr;
    }

    float acc[TM][TN];
#pragma unroll
    for (int i = 0; i < TM; i++)
#pragma unroll
        for (int j = 0; j < TN; j++) acc[i][j] = 0.f;

    for (int k0 = 0; k0 < D_IN; k0 += BK) {
        // Load A tile (gathered, transposed into smem)
#pragma unroll
        for (int i = 0; i < 2; i++) {
            int slot = tid + i * 256;
            int r  = slot >> 2;
            int kq = (slot & 3) * 4;
            float4 v = make_float4(0.f, 0.f, 0.f, 0.f);
            if (rowPtr[i]) v = *(const float4*)(rowPtr[i] + k0 + kq);
            As[kq + 0][r] = v.x;
            As[kq + 1][r] = v.y;
            As[kq + 2][r] = v.z;
            As[kq + 3][r] = v.w;
        }
        // Load B tile: 16 rows x 64 cols, one float4 per thread
        {
            int kr = tid >> 4;         // 0..15
            int nq = (tid & 15) * 4;
            float4 v = *(const float4*)(wE + (size_t)(k0 + kr) * D_OUT + nbase + nq);
            *(float4*)&Bs[kr][nq] = v;
        }
        __syncthreads();

#pragma unroll
        for (int kk = 0; kk < BK; kk++) {
            float a[TM];
#pragma unroll
            for (int i = 0; i < TM; i++) a[i] = As[kk][ty * TM + i];
            float4 b = *(const float4*)&Bs[kk][tx * TN];
#pragma unroll
            for (int i = 0; i < TM; i++) {
                acc[i][0] = fmaf(a[i], b.x, acc[i][0]);
                acc[i][1] = fmaf(a[i], b.y, acc[i][1]);
                acc[i][2] = fmaf(a[i], b.z, acc[i][2]);
                acc[i][3] = fmaf(a[i], b.w, acc[i][3]);
            }
        }
        __syncthreads();
    }

    // Epilogue
    float bias[TN];
#pragma unroll
    for (int j = 0; j < TN; j++)
        bias[j] = eb[e * D_OUT + nbase + tx * TN + j];

    const float* wts = g_wt + e * NT_MAX + mbase;
#pragma unroll
    for (int i = 0; i < TM; i++) {
        int r = ty * TM + i;
        if (mbase + r < cnt) {
            int   token = toks[r];
            float w     = wts[r];
            float* o = out + (size_t)token * D_OUT + nbase + tx * TN;
#pragma unroll
            for (int j = 0; j < TN; j++)
                atomicAdd(&o[j], w * (acc[i][j] + bias[j]));
        }
    }
}

extern "C" void kernel_launch(void* const* d_in, const int* in_sizes, int n_in,
                              void* d_out, int out_size) {
    const float* x  = (const float*)d_in[0];
    const float* gW = (const float*)d_in[1];
    const float* gb = (const float*)d_in[2];
    const float* eW = (const float*)d_in[3];
    const float* eb = (const float*)d_in[4];
    float* out = (float*)d_out;

    const int NT = in_sizes[0] / D_IN;   // 32768

    cudaMemsetAsync(d_out, 0, (size_t)out_size * sizeof(float), 0);
    zero_cnt_kernel<<<1, 32>>>();
    gate_kernel<<<(NT + 7) / 8, 256>>>(x, gW, gb, NT);

    dim3 grid(D_OUT / BN, (NT + BM - 1) / BM, NEXP);  // worst-case m-tiles, early exit
    moe_gemm_kernel<<<grid, 256>>>(x, eW, eb, out, NT);
}

// round 2
// speedup vs baseline: 2.4641x; 2.4641x over previous
#include <cuda_runtime.h>
#include <cuda_bf16.h>
#include <math.h>
#include <stdint.h>

#define D_IN   768
#define D_OUT  256
#define NEXP   8
#define NT_MAX 32768

// Scratch (device globals — no allocation allowed)
__device__ int   g_cnt[NEXP];
__device__ int   g_tok[NEXP * NT_MAX];
__device__ float g_wt [NEXP * NT_MAX];

__global__ void zero_cnt_kernel() {
    if (threadIdx.x < NEXP) g_cnt[threadIdx.x] = 0;
}

// One warp per token: gate logits -> softmax -> top2 -> append to expert lists.
__global__ void gate_kernel(const float* __restrict__ x,
                            const float* __restrict__ gW,
                            const float* __restrict__ gb,
                            int NT) {
    __shared__ float sW[D_IN * NEXP];  // 24 KB
    for (int i = threadIdx.x; i < D_IN * NEXP; i += blockDim.x) sW[i] = gW[i];
    __syncthreads();

    int warp = threadIdx.x >> 5;
    int lane = threadIdx.x & 31;
    int token = blockIdx.x * (blockDim.x >> 5) + warp;
    if (token >= NT) return;

    const float* xr = x + (size_t)token * D_IN;
    float acc[NEXP];
#pragma unroll
    for (int e = 0; e < NEXP; e++) acc[e] = 0.f;

#pragma unroll
    for (int j = 0; j < D_IN / 32; j++) {
        int k = lane + j * 32;
        float xv = xr[k];
        const float* w = &sW[k * NEXP];
#pragma unroll
        for (int e = 0; e < NEXP; e++) acc[e] = fmaf(xv, w[e], acc[e]);
    }
#pragma unroll
    for (int off = 16; off > 0; off >>= 1) {
#pragma unroll
        for (int e = 0; e < NEXP; e++)
            acc[e] += __shfl_xor_sync(0xffffffffu, acc[e], off);
    }

    if (lane == 0) {
        float l[NEXP];
#pragma unroll
        for (int e = 0; e < NEXP; e++) l[e] = acc[e] + gb[e];
        float m = l[0];
#pragma unroll
        for (int e = 1; e < NEXP; e++) m = fmaxf(m, l[e]);
        float s = 0.f, w[NEXP];
#pragma unroll
        for (int e = 0; e < NEXP; e++) { w[e] = __expf(l[e] - m); s += w[e]; }
        float inv = 1.f / s;

        int i0 = 0;
#pragma unroll
        for (int e = 1; e < NEXP; e++) if (l[e] > l[i0]) i0 = e;
        int i1 = (i0 == 0) ? 1 : 0;
#pragma unroll
        for (int e = 0; e < NEXP; e++)
            if (e != i0 && l[e] > l[i1]) i1 = e;

        float w0 = w[i0] * inv, w1 = w[i1] * inv;
        int p0 = atomicAdd(&g_cnt[i0], 1);
        g_tok[i0 * NT_MAX + p0] = token;
        g_wt [i0 * NT_MAX + p0] = w0;
        int p1 = atomicAdd(&g_cnt[i1], 1);
        g_tok[i1 * NT_MAX + p1] = token;
        g_wt [i1 * NT_MAX + p1] = w1;
    }
}

// ---------------------------------------------------------------------------
// TF32 tensor-core gathered GEMM per expert.
// BM=128, BN=128, BK=16. 256 threads = 8 warps in 4(m) x 2(n); warp tile 32x64.
// mma.sync.aligned.m16n8k8.row.col.f32.tf32.tf32.f32
// ---------------------------------------------------------------------------
#define BM 128
#define BN 128
#define BK 16
#define KTILES (D_IN / BK)   // 48

__device__ __forceinline__ uint32_t f2tf32(float f) {
    uint32_t r;
    asm("cvt.rna.tf32.f32 %0, %1;" : "=r"(r) : "f"(f));
    return r;
}

__global__ __launch_bounds__(256, 2)
void moe_gemm_tf32(const float* __restrict__ x,
                   const float* __restrict__ eW,
                   const float* __restrict__ eb,
                   float* __restrict__ out) {
    const int e = blockIdx.z;
    const int cnt = g_cnt[e];
    const int mbase = blockIdx.y * BM;
    if (mbase >= cnt) return;
    const int nbase = blockIdx.x * BN;

    // A: [row 0..127][k 0..15], pad to 20 -> conflict-free frag LDS (20r+k mod 32 distinct)
    // B: [k 0..15][n 0..127], pad to 136 -> stride ≡ 8 banks, conflict-free frag LDS
    __shared__ uint32_t As[2][BM][20];
    __shared__ uint32_t Bs[2][BK][136];

    const int tid  = threadIdx.x;
    const int warp = tid >> 5;
    const int lane = tid & 31;
    const int wm = warp >> 1;          // 0..3
    const int wn = warp & 1;           // 0..1
    const int grp = lane >> 2;         // 0..7
    const int tig = lane & 3;          // 0..3

    const int*   toks = g_tok + e * NT_MAX + mbase;
    const float* wts  = g_wt  + e * NT_MAX + mbase;
    const float* W    = eW + (size_t)e * D_IN * D_OUT;

    // A gather slots: 512 float4 slots = 128 rows x 4 chunks. slot = i*256+tid.
    const float* aPtr[2];
#pragma unroll
    for (int i = 0; i < 2; i++) {
        int slot = tid + i * 256;
        int r  = slot >> 2;
        int kc = slot & 3;
        aPtr[i] = (mbase + r < cnt) ? x + (size_t)toks[r] * D_IN + kc * 4 : nullptr;
    }
    // B slots: 512 float4 slots = 16 rows x 32 chunks. slot = i*256+tid.
    const float* bPtr[2];
#pragma unroll
    for (int i = 0; i < 2; i++) {
        int slot = tid + i * 256;
        int kr = slot >> 5;
        int c4 = slot & 31;
        bPtr[i] = W + (size_t)kr * D_OUT + nbase + c4 * 4;
    }

    float acc[2][8][4];
#pragma unroll
    for (int mi = 0; mi < 2; mi++)
#pragma unroll
        for (int ni = 0; ni < 8; ni++)
#pragma unroll
            for (int c = 0; c < 4; c++) acc[mi][ni][c] = 0.f;

    float4 aReg[2], bReg[2];

    // Prologue: load tile 0
#pragma unroll
    for (int i = 0; i < 2; i++) {
        aReg[i] = aPtr[i] ? *(const float4*)(aPtr[i]) : make_float4(0.f,0.f,0.f,0.f);
        bReg[i] = *(const float4*)(bPtr[i]);
    }
    {
#pragma unroll
        for (int i = 0; i < 2; i++) {
            int slot = tid + i * 256;
            int r = slot >> 2, kc = slot & 3;
            As[0][r][kc*4+0] = f2tf32(aReg[i].x);
            As[0][r][kc*4+1] = f2tf32(aReg[i].y);
            As[0][r][kc*4+2] = f2tf32(aReg[i].z);
            As[0][r][kc*4+3] = f2tf32(aReg[i].w);
            int kr = slot >> 5, c4 = slot & 31;
            Bs[0][kr][c4*4+0] = f2tf32(bReg[i].x);
            Bs[0][kr][c4*4+1] = f2tf32(bReg[i].y);
            Bs[0][kr][c4*4+2] = f2tf32(bReg[i].z);
            Bs[0][kr][c4*4+3] = f2tf32(bReg[i].w);
        }
    }
    __syncthreads();

    for (int t = 0; t < KTILES; t++) {
        const int cur = t & 1;
        const int nxt = cur ^ 1;
        const bool more = (t + 1 < KTILES);

        // Prefetch next tile into registers
        if (more) {
            int kOffA = (t + 1) * BK;
#pragma unroll
            for (int i = 0; i < 2; i++) {
                aReg[i] = aPtr[i] ? *(const float4*)(aPtr[i] + kOffA)
                                  : make_float4(0.f,0.f,0.f,0.f);
                bReg[i] = *(const float4*)(bPtr[i] + (size_t)(t + 1) * BK * D_OUT);
            }
        }

        // Compute: 2 k-steps of 8
#pragma unroll
        for (int kk = 0; kk < BK; kk += 8) {
            uint32_t a[2][4];
#pragma unroll
            for (int mi = 0; mi < 2; mi++) {
                int r0 = wm * 32 + mi * 16 + grp;
                a[mi][0] = As[cur][r0    ][kk + tig    ];
                a[mi][1] = As[cur][r0 + 8][kk + tig    ];
                a[mi][2] = As[cur][r0    ][kk + tig + 4];
                a[mi][3] = As[cur][r0 + 8][kk + tig + 4];
            }
#pragma unroll
            for (int ni = 0; ni < 8; ni++) {
                int n0 = wn * 64 + ni * 8 + grp;
                uint32_t b0 = Bs[cur][kk + tig    ][n0];
                uint32_t b1 = Bs[cur][kk + tig + 4][n0];
#pragma unroll
                for (int mi = 0; mi < 2; mi++) {
                    asm volatile(
                        "mma.sync.aligned.m16n8k8.row.col.f32.tf32.tf32.f32 "
                        "{%0,%1,%2,%3}, {%4,%5,%6,%7}, {%8,%9}, {%0,%1,%2,%3};"
                        : "+f"(acc[mi][ni][0]), "+f"(acc[mi][ni][1]),
                          "+f"(acc[mi][ni][2]), "+f"(acc[mi][ni][3])
                        : "r"(a[mi][0]), "r"(a[mi][1]), "r"(a[mi][2]), "r"(a[mi][3]),
                          "r"(b0), "r"(b1));
                }
            }
        }

        // Stage next tile into the other buffer
        if (more) {
#pragma unroll
            for (int i = 0; i < 2; i++) {
                int slot = tid + i * 256;
                int r = slot >> 2, kc = slot & 3;
                As[nxt][r][kc*4+0] = f2tf32(aReg[i].x);
                As[nxt][r][kc*4+1] = f2tf32(aReg[i].y);
                As[nxt][r][kc*4+2] = f2tf32(aReg[i].z);
                As[nxt][r][kc*4+3] = f2tf32(aReg[i].w);
                int kr = slot >> 5, c4 = slot & 31;
                Bs[nxt][kr][c4*4+0] = f2tf32(bReg[i].x);
                Bs[nxt][kr][c4*4+1] = f2tf32(bReg[i].y);
                Bs[nxt][kr][c4*4+2] = f2tf32(bReg[i].z);
                Bs[nxt][kr][c4*4+3] = f2tf32(bReg[i].w);
            }
            __syncthreads();
        }
    }

    // Epilogue: out[token] += w * (acc + bias), vectorized f32x2 reductions.
#pragma unroll
    for (int mi = 0; mi < 2; mi++) {
        int rt0 = wm * 32 + mi * 16 + grp;      // rows rt0 and rt0+8
#pragma unroll
        for (int half = 0; half < 2; half++) {
            int rt = rt0 + half * 8;
            if (mbase + rt < cnt) {
                int   token = toks[rt];
                float w     = wts[rt];
                float* orow = out + (size_t)token * D_OUT;
#pragma unroll
                for (int ni = 0; ni < 8; ni++) {
                    int col = nbase + wn * 64 + ni * 8 + tig * 2;
                    float b0 = eb[e * D_OUT + col];
                    float b1 = eb[e * D_OUT + col + 1];
                    float v0 = w * (acc[mi][ni][half*2 + 0] + b0);
                    float v1 = w * (acc[mi][ni][half*2 + 1] + b1);
                    asm volatile("red.global.add.v2.f32 [%0], {%1, %2};"
                                 :: "l"(orow + col), "f"(v0), "f"(v1)
                                 : "memory");
                }
            }
        }
    }
}

extern "C" void kernel_launch(void* const* d_in, const int* in_sizes, int n_in,
                              void* d_out, int out_size) {
    const float* x  = (const float*)d_in[0];
    const float* gW = (const float*)d_in[1];
    const float* gb = (const float*)d_in[2];
    const float* eW = (const float*)d_in[3];
    const float* eb = (const float*)d_in[4];
    float* out = (float*)d_out;

    const int NT = in_sizes[0] / D_IN;   // 32768

    cudaMemsetAsync(d_out, 0, (size_t)out_size * sizeof(float), 0);
    zero_cnt_kernel<<<1, 32>>>();
    gate_kernel<<<(NT + 7) / 8, 256>>>(x, gW, gb, NT);

    dim3 grid(D_OUT / BN, (NT + BM - 1) / BM, NEXP);  // worst-case m-tiles, early exit
    moe_gemm_tf32<<<grid, 256>>>(x, eW, eb, out);
}